// round 14
// baseline (speedup 1.0000x reference)
#include <cuda_runtime.h>
#include <cuda_fp16.h>
#include <cstdint>

// ============================================================================
// GFDreConv: out[b,o,h,w] = sum_{k<2304} W[o,k] * X[k](b,h,w)
// fp16 mma.sync m16n8k16 f32-acc for the 8 gathered sample groups (K=2048,
// 32 chunks) + FFMA/HFMA2 co-execution of the identity group (K=256, 8 k per
// chunk) on the otherwise-idle FMA pipe. Tensor instruction floor drops 36->32
// chunks. f16 pairwise partials folded to f32 every 4 chunks (err ~1e-4 RMS).
// ============================================================================

#define KTOT 2304
#define BK   64
#define NCT  32            // tensor chunks (s=1..8)

__device__ __align__(16) __half g_Wh[256 * KTOT];
__device__ __align__(16) __half g_Fh[8ull * 4096 * 256];     // 16 MB, L2-resident

#define LDS_ROW 72
#define A_STG_B (128 * LDS_ROW * 2)        // 18432
#define B_STG_B (64 * LDS_ROW * 2)         // 9216
#define OFF_B0  (2 * A_STG_B)              // 36864
#define OFF_IDA (OFF_B0 + 2 * B_STG_B)     // 55296  (2 stages x 2048)
#define OFF_IDB (OFF_IDA + 2 * 2048)       // 59392  (2 stages x 1024)
#define OFF_GO  (OFF_IDB + 2 * 1024)       // 61440  (8*64 u16)
#define SMEM_TOTAL (OFF_GO + 8 * 64 * 2)   // 62464 B -> 2 CTAs/SM

#define FPREP_SMEM (256 * 64 * 4)          // 64 KB dynamic

__device__ __forceinline__ uint32_t s2u(const void* p) {
    uint32_t a;
    asm("{ .reg .u64 t; cvta.to.shared.u64 t, %1; cvt.u32.u64 %0, t; }" : "=r"(a) : "l"(p));
    return a;
}
__device__ __forceinline__ void cpa(uint32_t d, const void* g) {
    asm volatile("cp.async.cg.shared.global [%0], [%1], 16;" :: "r"(d), "l"(g));
}

#define LDSM4(r, a)                                                            \
    asm volatile("ldmatrix.sync.aligned.m8n8.x4.shared.b16 {%0,%1,%2,%3},[%4];"\
                 : "=r"((r)[0]), "=r"((r)[1]), "=r"((r)[2]), "=r"((r)[3])      \
                 : "r"(a))
#define MMA(c, a, b0, b1)                                                      \
    asm volatile("mma.sync.aligned.m16n8k16.row.col.f32.f16.f16.f32 "          \
                 "{%0,%1,%2,%3},{%4,%5,%6,%7},{%8,%9},{%0,%1,%2,%3};"          \
                 : "+f"((c)[0]), "+f"((c)[1]), "+f"((c)[2]), "+f"((c)[3])      \
                 : "r"((a)[0]), "r"((a)[1]), "r"((a)[2]), "r"((a)[3]),         \
                   "r"(b0), "r"(b1))

// ---------------------------------------------------------------------------
// Fused prep. Blocks [0,512): transpose feat -> [b][sp][c] fp16.
// Blocks [512,800): W -> fp16.
// ---------------------------------------------------------------------------
__global__ void __launch_bounds__(256, 1)
prep(const float* __restrict__ feat, const float* __restrict__ Wc) {
    const int t = threadIdx.x;
    if (blockIdx.x >= 512) {
        const int base = (blockIdx.x - 512) * 2048 + t * 8;
        float4 v0 = *(const float4*)(Wc + base);
        float4 v1 = *(const float4*)(Wc + base + 4);
        __half hb[8];
        hb[0] = __float2half(v0.x); hb[1] = __float2half(v0.y);
        hb[2] = __float2half(v0.z); hb[3] = __float2half(v0.w);
        hb[4] = __float2half(v1.x); hb[5] = __float2half(v1.y);
        hb[6] = __float2half(v1.z); hb[7] = __float2half(v1.w);
        *(uint4*)(g_Wh + base) = *(const uint4*)hb;
        return;
    }
    extern __shared__ float tile[];
    const int b = blockIdx.x >> 6;
    const int y = blockIdx.x & 63;
    const float* src = feat + (((size_t)b * 256) * 64 + y) * 64;
    for (int idx = t; idx < 256 * 64; idx += 256) {
        int c = idx >> 6, x = idx & 63;
        tile[idx] = src[(size_t)c * 4096 + x];
    }
    __syncthreads();
    const int x = t >> 2;
    const int c0 = (t & 3) * 64;
    uint4* dh = (uint4*)(g_Fh + ((size_t)b * 4096 + (size_t)y * 64 + x) * 256 + c0);
#pragma unroll
    for (int j = 0; j < 8; j++) {
        __half hbuf[8];
#pragma unroll
        for (int i = 0; i < 8; i++)
            hbuf[i] = __float2half(tile[(c0 + j * 8 + i) * 64 + x]);
        dh[j] = *(const uint4*)hbuf;
    }
}

// ---------------------------------------------------------------------------
// Main: 1024 CTAs (2 M x 512 N-blocks of 64), 8 warps (4Mx2N, 32x32 tiles),
// 2 CTAs/SM, 2-stage cp.async pipeline. Tensor: 32 gathered chunks.
// FFMA: identity K=256 at 8 k/chunk via HFMA2 partials.
// ---------------------------------------------------------------------------
__global__ void __launch_bounds__(256, 2)
gfd_mma(const int* __restrict__ sx, const int* __restrict__ sy,
        float* __restrict__ out) {
    extern __shared__ char sm[];
    const uint32_t sb = s2u(sm);

    const int t = threadIdx.x, lane = t & 31, wid = t >> 5;
    const int wm = wid & 3, wn = wid >> 2;
    const int mblk = blockIdx.x & 1;
    const int r = blockIdx.x >> 1;
    const int b = r >> 6;
    const int n0 = (r & 63) * 64;
    const int g = lane >> 2, tig = lane & 3;

    uint16_t* gofs = (uint16_t*)(sm + OFF_GO);
    for (int i = t; i < 8 * 64; i += 256) {
        int s = i >> 6, nn = i & 63;          // s = sample 0..7 (orig s-1)
        int idx = (n0 + nn) * 8 + s;
        gofs[i] = (uint16_t)((sy[idx] - 1) * 64 + (sx[idx] - 1));
    }
    __syncthreads();

    const int a_row = t >> 1, a_h = (t & 1) * 32;
    const int b_row = t >> 2, b_q = (t & 3) * 16;
    const size_t fb = (size_t)b * 4096 * 256;
    const __half* wbase = g_Wh + (size_t)(mblk * 128) * KTOT;

    const uint32_t a_off0 =
        ((uint32_t)(wm * 32 + (lane & 15)) * LDS_ROW + (lane >> 4) * 8) * 2;
    const uint32_t a_off1 = a_off0 + (uint32_t)(16 * LDS_ROW) * 2;
    const uint32_t b_off0 =
        ((uint32_t)(wn * 32 + (lane >> 4) * 8 + (lane & 7)) * LDS_ROW +
         ((lane >> 3) & 1) * 8) * 2;
    const uint32_t b_off1 = b_off0 + (uint32_t)(16 * LDS_ROW) * 2;

    // FFMA operand smem offsets (16B per row/col)
    uint32_t ida_ro[4];   // ar = i*2+h -> row = wm*32 + i*16 + h*8 + g
#pragma unroll
    for (int ar = 0; ar < 4; ar++)
        ida_ro[ar] = (uint32_t)((wm * 32 + (ar >> 1) * 16 + (ar & 1) * 8 + g) * 16);
    uint32_t idb_co[8];   // bc = j*2+p -> col = wn*32 + j*8 + tig*2 + p
#pragma unroll
    for (int bc = 0; bc < 8; bc++)
        idb_co[bc] = (uint32_t)((wn * 32 + (bc >> 1) * 8 + tig * 2 + (bc & 1)) * 16);

    float acc[2][4][4];
#pragma unroll
    for (int i = 0; i < 2; i++)
#pragma unroll
        for (int j = 0; j < 4; j++)
#pragma unroll
            for (int q = 0; q < 4; q++) acc[i][j][q] = 0.0f;

    __half2 hacc[4][8];
    const __half2 hz = __floats2half2_rn(0.0f, 0.0f);
#pragma unroll
    for (int ar = 0; ar < 4; ar++)
#pragma unroll
        for (int bc = 0; bc < 8; bc++) hacc[ar][bc] = hz;

    auto issue = [&](int kc) {
        const int stg = kc & 1;
        const int s = kc >> 2;                 // sample 0..7
        const int c0 = (kc & 3) * 64;
        // A tile (gathered-group weights: original k = 256 + kc*64 ...)
        const uint32_t da = sb + stg * A_STG_B + ((uint32_t)a_row * LDS_ROW + a_h) * 2;
        const __half* ga = wbase + (size_t)a_row * KTOT + 256 + kc * BK + a_h;
#pragma unroll
        for (int q = 0; q < 4; q++) cpa(da + q * 16, ga + q * 8);
        // B tile (gathered rows)
        const int sp = gofs[s * 64 + b_row];
        const uint32_t db = sb + OFF_B0 + stg * B_STG_B +
                            ((uint32_t)b_row * LDS_ROW + b_q) * 2;
        const __half* gb = g_Fh + fb + (size_t)sp * 256 + c0 + b_q;
#pragma unroll
        for (int q = 0; q < 2; q++) cpa(db + q * 16, gb + q * 8);
        // identity micro-tiles: 8 k (= channels kc*8..kc*8+7)
        const int c8 = kc * 8;
        if (t < 128) {
            cpa(sb + OFF_IDA + stg * 2048 + (uint32_t)t * 16,
                g_Wh + (size_t)(mblk * 128 + t) * KTOT + c8);
        } else if (t < 192) {
            const int nn = t - 128;
            cpa(sb + OFF_IDB + stg * 1024 + (uint32_t)nn * 16,
                g_Fh + fb + (size_t)(n0 + nn) * 256 + c8);
        }
        asm volatile("cp.async.commit_group;" ::: "memory");
    };

    issue(0);

    for (int kc = 0; kc < NCT; kc++) {
        asm volatile("cp.async.wait_group 0;" ::: "memory");
        __syncthreads();
        if (kc + 1 < NCT) issue(kc + 1);

        const int stg = kc & 1;
        const uint32_t aP = sb + stg * A_STG_B;
        const uint32_t bP = sb + OFF_B0 + stg * B_STG_B;

        // ---- tensor path: 32 MMAs (fire-and-forget into acc) ----
#pragma unroll
        for (int kk = 0; kk < 4; kk++) {
            const uint32_t ko = (uint32_t)(kk * 16) * 2;
            uint32_t ah[2][4], bf[2][4];
            LDSM4(ah[0], aP + a_off0 + ko);
            LDSM4(ah[1], aP + a_off1 + ko);
            LDSM4(bf[0], bP + b_off0 + ko);
            LDSM4(bf[1], bP + b_off1 + ko);
#pragma unroll
            for (int j2 = 0; j2 < 2; j2++) {
#pragma unroll
                for (int i = 0; i < 2; i++) {
                    MMA(acc[i][j2 * 2],     ah[i], bf[j2][0], bf[j2][1]);
                    MMA(acc[i][j2 * 2 + 1], ah[i], bf[j2][2], bf[j2][3]);
                }
            }
        }

        // ---- FFMA path: identity 8-k micro-GEMM on the FMA pipe ----
        {
            const char* idA = sm + OFF_IDA + stg * 2048;
            const char* idB = sm + OFF_IDB + stg * 1024;
            __half2 av[4][4];
#pragma unroll
            for (int ar = 0; ar < 4; ar++) {
                uint4 v = *(const uint4*)(idA + ida_ro[ar]);
                av[ar][0] = *(const __half2*)&v.x;
                av[ar][1] = *(const __half2*)&v.y;
                av[ar][2] = *(const __half2*)&v.z;
                av[ar][3] = *(const __half2*)&v.w;
            }
#pragma unroll
            for (int bc = 0; bc < 8; bc++) {
                uint4 v = *(const uint4*)(idB + idb_co[bc]);
                __half2 bv0 = *(const __half2*)&v.x;
                __half2 bv1 = *(const __half2*)&v.y;
                __half2 bv2 = *(const __half2*)&v.z;
                __half2 bv3 = *(const __half2*)&v.w;
#pragma unroll
                for (int ar = 0; ar < 4; ar++) {
                    __half2 h = hacc[ar][bc];
                    h = __hfma2(av[ar][0], bv0, h);
                    h = __hfma2(av[ar][1], bv1, h);
                    h = __hfma2(av[ar][2], bv2, h);
                    h = __hfma2(av[ar][3], bv3, h);
                    hacc[ar][bc] = h;
                }
            }
        }

        // ---- fold f16 partials into f32 acc every 4 chunks ----
        if ((kc & 3) == 3) {
#pragma unroll
            for (int i = 0; i < 2; i++)
#pragma unroll
                for (int j = 0; j < 4; j++)
#pragma unroll
                    for (int h = 0; h < 2; h++)
#pragma unroll
                        for (int p = 0; p < 2; p++) {
                            float2 f = __half22float2(hacc[i * 2 + h][j * 2 + p]);
                            acc[i][j][h * 2 + p] += f.x + f.y;
                            hacc[i * 2 + h][j * 2 + p] = hz;
                        }
        }
    }

    // ---- epilogue ----
#pragma unroll
    for (int i = 0; i < 2; i++) {
        const int o = mblk * 128 + wm * 32 + i * 16 + g;
        float* obase = out + ((size_t)b * 256 + o) * 4096;
#pragma unroll
        for (int j = 0; j < 4; j++) {
            const int sp = n0 + wn * 32 + j * 8 + tig * 2;
            *(float2*)(obase + sp) = make_float2(acc[i][j][0], acc[i][j][1]);
            *(float2*)(obase + 8 * 4096 + sp) = make_float2(acc[i][j][2], acc[i][j][3]);
        }
    }
}

// ============================================================================
extern "C" void kernel_launch(void* const* d_in, const int* in_sizes, int n_in,
                              void* d_out, int out_size) {
    const float* feat = (const float*)d_in[0];  // (8,256,64,64) f32
    const float* Wc   = (const float*)d_in[1];  // (256,2304) f32
    const int*   sx   = (const int*)d_in[2];    // (64,64,8) i32
    const int*   sy   = (const int*)d_in[3];    // (64,64,8) i32
    float*       out  = (float*)d_out;          // (8,256,64,64) f32

    static bool attr_set = false;
    if (!attr_set) {
        cudaFuncSetAttribute(gfd_mma, cudaFuncAttributeMaxDynamicSharedMemorySize,
                             SMEM_TOTAL);
        cudaFuncSetAttribute(prep, cudaFuncAttributeMaxDynamicSharedMemorySize,
                             FPREP_SMEM);
        attr_set = true;
    }

    prep<<<800, 256, FPREP_SMEM>>>(feat, Wc);
    gfd_mma<<<1024, 256, SMEM_TOTAL>>>(sx, sy, out);
}

// round 15
// speedup vs baseline: 1.1965x; 1.1965x over previous
#include <cuda_runtime.h>
#include <cuda_fp16.h>
#include <cstdint>

// ============================================================================
// GFDreConv: out[b,o,h,w] = sum_{k<2304} W[o,k] * X[k](b,h,w)
// Single-pass fp16 mma.sync m16n8k16, fp32 accum (rel_err 2.93e-4 < 1e-3).
// feat transposed to [b][sp][c] fp16 so gathered K-runs are contiguous.
// Round 15: round-10 champion + global gather-table precompute in prep +
// prologue overlap (issue(0) before gofs load; identity group needs no table).
// Main kernel is at the sm_100 mma.sync fallback-HMMA floor (rt~22/SMSP).
// ============================================================================

#define KTOT 2304
#define BK   64
#define NC   (KTOT / BK)   // 36

__device__ __align__(16) __half   g_Wh[256 * KTOT];
__device__ __align__(16) __half   g_Fh[8ull * 4096 * 256];   // 16 MB, L2-resident
__device__ __align__(16) uint16_t g_goff[8 * 4096];          // [s][sp] gather table

// smem rows: 64 halves + 8 pad = 72 halves (144B), conflict-free for ldmatrix.
#define LDS_ROW 72
#define A_STG_B (128 * LDS_ROW * 2)        // 18432
#define B_STG_B (64 * LDS_ROW * 2)         // 9216
#define OFF_B0  (2 * A_STG_B)
#define OFF_GO  (2 * A_STG_B + 2 * B_STG_B)        // 55296
#define SMEM_TOTAL (OFF_GO + 8 * 64 * 2)   // 56320 B

#define FPREP_SMEM (256 * 64 * 4)          // 64 KB dynamic

__device__ __forceinline__ uint32_t s2u(const void* p) {
    uint32_t a;
    asm("{ .reg .u64 t; cvta.to.shared.u64 t, %1; cvt.u32.u64 %0, t; }" : "=r"(a) : "l"(p));
    return a;
}
__device__ __forceinline__ void cpa(uint32_t d, const void* g) {
    asm volatile("cp.async.cg.shared.global [%0], [%1], 16;" :: "r"(d), "l"(g));
}

#define LDSM4(r, a)                                                            \
    asm volatile("ldmatrix.sync.aligned.m8n8.x4.shared.b16 {%0,%1,%2,%3},[%4];"\
                 : "=r"((r)[0]), "=r"((r)[1]), "=r"((r)[2]), "=r"((r)[3])      \
                 : "r"(a))
#define MMA(c, a, b0, b1)                                                      \
    asm volatile("mma.sync.aligned.m16n8k16.row.col.f32.f16.f16.f32 "          \
                 "{%0,%1,%2,%3},{%4,%5,%6,%7},{%8,%9},{%0,%1,%2,%3};"          \
                 : "+f"((c)[0]), "+f"((c)[1]), "+f"((c)[2]), "+f"((c)[3])      \
                 : "r"((a)[0]), "r"((a)[1]), "r"((a)[2]), "r"((a)[3]),         \
                   "r"(b0), "r"(b1))

// ---------------------------------------------------------------------------
// Fused prep. Blocks [0,512): transpose feat (b,y slice) -> [b][sp][c] fp16.
// Blocks [512,800): W -> fp16.  Blocks [800,832): gather table.
// ---------------------------------------------------------------------------
__global__ void __launch_bounds__(256, 1)
prep(const float* __restrict__ feat, const float* __restrict__ Wc,
     const int* __restrict__ sx, const int* __restrict__ sy) {
    const int t = threadIdx.x;
    if (blockIdx.x >= 800) {
        const int base = (blockIdx.x - 800) * 1024 + t;
#pragma unroll
        for (int q = 0; q < 4; q++) {
            const int e = base + q * 256;         // e = s1*4096 + sp
            const int s1 = e >> 12;
            const int sp = e & 4095;
            const int idx = sp * 8 + s1;
            g_goff[e] = (uint16_t)((sy[idx] - 1) * 64 + (sx[idx] - 1));
        }
        return;
    }
    if (blockIdx.x >= 512) {
        const int base = (blockIdx.x - 512) * 2048 + t * 8;
        float4 v0 = *(const float4*)(Wc + base);
        float4 v1 = *(const float4*)(Wc + base + 4);
        __half hb[8];
        hb[0] = __float2half(v0.x); hb[1] = __float2half(v0.y);
        hb[2] = __float2half(v0.z); hb[3] = __float2half(v0.w);
        hb[4] = __float2half(v1.x); hb[5] = __float2half(v1.y);
        hb[6] = __float2half(v1.z); hb[7] = __float2half(v1.w);
        *(uint4*)(g_Wh + base) = *(const uint4*)hb;
        return;
    }
    extern __shared__ float tile[];      // [c][x] 256*64 f32
    const int b = blockIdx.x >> 6;
    const int y = blockIdx.x & 63;
    const float* src = feat + (((size_t)b * 256) * 64 + y) * 64;
    for (int idx = t; idx < 256 * 64; idx += 256) {
        int c = idx >> 6, x = idx & 63;
        tile[idx] = src[(size_t)c * 4096 + x];
    }
    __syncthreads();
    const int x = t >> 2;
    const int c0 = (t & 3) * 64;
    uint4* dh = (uint4*)(g_Fh + ((size_t)b * 4096 + (size_t)y * 64 + x) * 256 + c0);
#pragma unroll
    for (int j = 0; j < 8; j++) {
        __half hbuf[8];
#pragma unroll
        for (int i = 0; i < 8; i++)
            hbuf[i] = __float2half(tile[(c0 + j * 8 + i) * 64 + x]);
        dh[j] = *(const uint4*)hbuf;
    }
}

// ---------------------------------------------------------------------------
// Main: 1024 CTAs (2 M-blocks x 512 N-blocks of 64), 256 threads,
// 8 warps (4M x 2N), warp tile 32x32, 2-stage pipeline.
// ---------------------------------------------------------------------------
__global__ void __launch_bounds__(256, 2)
gfd_mma(float* __restrict__ out) {
    extern __shared__ char sm[];
    const uint32_t sb = s2u(sm);

    const int t = threadIdx.x, lane = t & 31, wid = t >> 5;
    const int wm = wid & 3, wn = wid >> 2;           // 4M x 2N
    const int mblk = blockIdx.x & 1;
    const int r = blockIdx.x >> 1;
    const int b = r >> 6;
    const int n0 = (r & 63) * 64;

    // A load map: row = t>>1 (0..127), 64B half-row; B: row = t>>2 (0..63), 32B
    const int a_row = t >> 1, a_h = (t & 1) * 32;
    const int b_row = t >> 2, b_q = (t & 3) * 16;
    const size_t fb = (size_t)b * 4096 * 256;
    const __half* wbase = g_Wh + (size_t)(mblk * 128) * KTOT;

    uint16_t* gofs = (uint16_t*)(sm + OFF_GO);

    auto issue = [&](int kc) {
        const int stg = kc & 1;
        const int k0 = kc * BK;
        const int s = kc >> 2;                 // 0 = identity, 1..8 gathered
        const int c0 = (kc & 3) * 64;
        // A
        const uint32_t da = sb + stg * A_STG_B + ((uint32_t)a_row * LDS_ROW + a_h) * 2;
        const __half* ga = wbase + (size_t)a_row * KTOT + k0 + a_h;
#pragma unroll
        for (int q = 0; q < 4; q++) cpa(da + q * 16, ga + q * 8);
        // B (gathered; s=0 needs no table)
        const int sp = (s == 0) ? (n0 + b_row) : (int)gofs[(s - 1) * 64 + b_row];
        const uint32_t db = sb + OFF_B0 + stg * B_STG_B +
                            ((uint32_t)b_row * LDS_ROW + b_q) * 2;
        const __half* gb = g_Fh + fb + (size_t)sp * 256 + c0 + b_q;
#pragma unroll
        for (int q = 0; q < 2; q++) cpa(db + q * 16, gb + q * 8);
        asm volatile("cp.async.commit_group;" ::: "memory");
    };

    // prologue overlap: chunk 0 (identity) in flight while gofs slice loads
    issue(0);
    for (int i = t; i < 8 * 64; i += 256)
        gofs[i] = g_goff[(i >> 6) * 4096 + n0 + (i & 63)];

    // ldmatrix offsets
    const uint32_t a_off0 =
        ((uint32_t)(wm * 32 + (lane & 15)) * LDS_ROW + (lane >> 4) * 8) * 2;
    const uint32_t a_off1 = a_off0 + (uint32_t)(16 * LDS_ROW) * 2;
    const uint32_t b_off0 =
        ((uint32_t)(wn * 32 + (lane >> 4) * 8 + (lane & 7)) * LDS_ROW +
         ((lane >> 3) & 1) * 8) * 2;
    const uint32_t b_off1 = b_off0 + (uint32_t)(16 * LDS_ROW) * 2;

    float acc[2][4][4];
#pragma unroll
    for (int i = 0; i < 2; i++)
#pragma unroll
        for (int j = 0; j < 4; j++)
#pragma unroll
            for (int q = 0; q < 4; q++) acc[i][j][q] = 0.0f;

    for (int kc = 0; kc < NC; kc++) {
        asm volatile("cp.async.wait_group 0;" ::: "memory");
        __syncthreads();                // also publishes gofs before issue(4)
        if (kc + 1 < NC) issue(kc + 1);

        const int stg = kc & 1;
        const uint32_t aP = sb + stg * A_STG_B;
        const uint32_t bP = sb + OFF_B0 + stg * B_STG_B;

#pragma unroll
        for (int kk = 0; kk < 4; kk++) {
            const uint32_t ko = (uint32_t)(kk * 16) * 2;
            uint32_t ah[2][4], bf[2][4];
            LDSM4(ah[0], aP + a_off0 + ko);
            LDSM4(ah[1], aP + a_off1 + ko);
            LDSM4(bf[0], bP + b_off0 + ko);
            LDSM4(bf[1], bP + b_off1 + ko);
#pragma unroll
            for (int j2 = 0; j2 < 2; j2++) {
#pragma unroll
                for (int i = 0; i < 2; i++) {
                    MMA(acc[i][j2 * 2],     ah[i], bf[j2][0], bf[j2][1]);
                    MMA(acc[i][j2 * 2 + 1], ah[i], bf[j2][2], bf[j2][3]);
                }
            }
        }
    }

    const int g = lane >> 2, tig = lane & 3;
#pragma unroll
    for (int i = 0; i < 2; i++) {
        const int o = mblk * 128 + wm * 32 + i * 16 + g;
        float* obase = out + ((size_t)b * 256 + o) * 4096;
#pragma unroll
        for (int j = 0; j < 4; j++) {
            const int sp = n0 + wn * 32 + j * 8 + tig * 2;
            *(float2*)(obase + sp) = make_float2(acc[i][j][0], acc[i][j][1]);
            *(float2*)(obase + 8 * 4096 + sp) = make_float2(acc[i][j][2], acc[i][j][3]);
        }
    }
}

// ============================================================================
extern "C" void kernel_launch(void* const* d_in, const int* in_sizes, int n_in,
                              void* d_out, int out_size) {
    const float* feat = (const float*)d_in[0];  // (8,256,64,64) f32
    const float* Wc   = (const float*)d_in[1];  // (256,2304) f32
    const int*   sx   = (const int*)d_in[2];    // (64,64,8) i32
    const int*   sy   = (const int*)d_in[3];    // (64,64,8) i32
    float*       out  = (float*)d_out;          // (8,256,64,64) f32

    static bool attr_set = false;
    if (!attr_set) {
        cudaFuncSetAttribute(gfd_mma, cudaFuncAttributeMaxDynamicSharedMemorySize,
                             SMEM_TOTAL);
        cudaFuncSetAttribute(prep, cudaFuncAttributeMaxDynamicSharedMemorySize,
                             FPREP_SMEM);
        attr_set = true;
    }

    prep<<<832, 256, FPREP_SMEM>>>(feat, Wc, sx, sy);
    gfd_mma<<<1024, 256, SMEM_TOTAL>>>(out);
}